// round 5
// baseline (speedup 1.0000x reference)
#include <cuda_runtime.h>
#include <cuda_fp16.h>

#define T_STEPS 4096
#define HID     2048
#define DIN     66
#define PRE     64
#define OUT_T   (T_STEPS - PRE)   // 4032
#define G4      8192              // 4*HID gate rows
#define NBLK    128
#define NTHR    512
#define UNITS   16                // hidden units per block per layer
#define KB      4096              // layer2 K: [h1 ; h2]
#define NIT_A   8                 // 2048 / 256
#define PK      1536              // pinned columns of W2 per row (in SMEM)
#define PIN_IT  6                 // PK / 256
#define OB_ROWS 4

#define PIN_BYTES  (64 * PK * 2)                    // 196608
#define DYN_BYTES  (PIN_BYTES + HID * 2 + KB * 2)   // + vA(4KB) + vB(8KB) = 208896

// ---------------- static device scratch (no allocations allowed) ----------------
__device__ __half g_W1[(size_t)G4 * HID];       // 33.5 MB  W_hh1 fp16
__device__ __half g_W2[(size_t)G4 * KB];        // 67.1 MB  [W_ih2 | W_hh2] fp16
__device__ float  g_b2[G4];
__device__ float  g_gx[(size_t)T_STEPS * G4];   // 134 MB: x@W_ih1^T + b1, block-permuted
__device__ __half g_h1h[2][HID];                // parity double-buffered h1 (half)
__device__ __half g_h2h[2][HID];                // parity double-buffered h2 (half)
__device__ float  g_hist[(size_t)T_STEPS * HID];// h2 history (fp32) for output GEMM
__device__ unsigned g_cnt;                      // grid barrier counter (monotonic)

// row index within block (k=0..63) -> global gate row j
__device__ __forceinline__ int row_j(int k, int base) {
    return ((k >> 4) * HID) + base + (k & 15);
}

// ---------------- prep kernels ----------------
__global__ void prep_w1(const float* __restrict__ Whh1) {
    size_t i = (size_t)blockIdx.x * blockDim.x + threadIdx.x;
    if (i < (size_t)G4 * HID) g_W1[i] = __float2half(Whh1[i]);
}

__global__ void prep_w2(const float* __restrict__ Wih2, const float* __restrict__ Whh2) {
    size_t i = (size_t)blockIdx.x * blockDim.x + threadIdx.x;
    if (i >= (size_t)G4 * KB) return;
    int j = (int)(i / KB);
    int c = (int)(i % KB);
    float v = (c < HID) ? Wih2[(size_t)j * HID + c]
                        : Whh2[(size_t)j * HID + (c - HID)];
    g_W2[i] = __float2half(v);
}

__global__ void prep_misc(const float* __restrict__ bi2, const float* __restrict__ bh2) {
    int i = blockIdx.x * blockDim.x + threadIdx.x;
    if (i < G4) g_b2[i] = bi2[i] + bh2[i];
    if (i < HID) {
        __half z = __float2half(0.f);
        g_h1h[0][i] = z; g_h1h[1][i] = z;
        g_h2h[0][i] = z; g_h2h[1][i] = z;
    }
    if (i == 0) g_cnt = 0u;
}

// gates_x[t, blk, k] = b1[j] + sum_c y[t,c] * W_ih1[j,c]   (block-local row order k)
// grid: (NBLK, 4) — y-dim splits the time range 4-way.
__global__ void prep_gx(const float* __restrict__ y, const float* __restrict__ Wih1,
                        const float* __restrict__ bi1, const float* __restrict__ bh1) {
    __shared__ float sW[64][68];   // padded to 17 float4 per row
    __shared__ float sb[64];
    const int b = blockIdx.x, base = b * UNITS;
    for (int idx = threadIdx.x; idx < 64 * 68; idx += NTHR) {
        int k = idx / 68, c = idx % 68;
        sW[k][c] = (c < DIN) ? Wih1[(size_t)row_j(k, base) * DIN + c] : 0.f;
    }
    if (threadIdx.x < 64) {
        int j = row_j(threadIdx.x, base);
        sb[threadIdx.x] = bi1[j] + bh1[j];
    }
    __syncthreads();
    const int t0 = blockIdx.y * (T_STEPS / 4);
    for (int t = t0 + threadIdx.x; t < t0 + T_STEPS / 4; t += NTHR) {
        float xv[68];
#pragma unroll
        for (int c = 0; c < DIN; ++c) xv[c] = y[(size_t)t * DIN + c];
        xv[66] = 0.f; xv[67] = 0.f;
        float* outp = &g_gx[((size_t)t * NBLK + b) * 64];
        for (int k = 0; k < 64; ++k) {
            float s = sb[k];
#pragma unroll
            for (int c4 = 0; c4 < 17; ++c4) {
                float4 w = *(const float4*)&sW[k][c4 * 4];
                s += w.x * xv[c4*4] + w.y * xv[c4*4+1] + w.z * xv[c4*4+2] + w.w * xv[c4*4+3];
            }
            outp[k] = s;
        }
    }
}

// ---------------- math helpers ----------------
__device__ __forceinline__ float sigmoidf_(float x) { return 1.f / (1.f + __expf(-x)); }
__device__ __forceinline__ float tanhf_(float x) {
    float e = __expf(-2.f * fabsf(x));
    float r = (1.f - e) / (1.f + e);
    return (x < 0.f) ? -r : r;
}

#define MACC(wv, ACC)                                                       \
    {                                                                       \
        __half2 a = __hmul2(*(__half2*)&wv.x, h0);                          \
        a = __hfma2(*(__half2*)&wv.y, h1, a);                               \
        a = __hfma2(*(__half2*)&wv.z, h2, a);                               \
        a = __hfma2(*(__half2*)&wv.w, h3, a);                               \
        float2 f = __half22float2(a);                                       \
        ACC += f.x; ACC += f.y;                                             \
    }
#define ROWSTEP_G(P, ACC) { uint4 wv = __ldcg((const uint4*)(P)); MACC(wv, ACC) }
#define ROWSTEP_S(P, ACC) { uint4 wv = *(const uint4*)(P);        MACC(wv, ACC) }
#define LOADV(vs, idx)                                                      \
    uint4 hv = (vs)[idx];                                                   \
    __half2 h0 = *(__half2*)&hv.x, h1 = *(__half2*)&hv.y,                   \
            h2 = *(__half2*)&hv.z, h3 = *(__half2*)&hv.w;

__device__ __forceinline__ void reduce_store(float v, float add, float* gates, int k) {
#pragma unroll
    for (int o = 16; o > 0; o >>= 1) v += __shfl_xor_sync(0xffffffffu, v, o);
    if ((threadIdx.x & 31) == 0) gates[k] = v + add;
}

// ---------------- main persistent recurrent kernel ----------------
__global__ void __launch_bounds__(NTHR, 1) lstm_main() {
    extern __shared__ __align__(16) unsigned char dynsmem[];
    __half* sW2 = (__half*)dynsmem;                       // 64 x PK pinned W2 slice
    __half* vA  = (__half*)(dynsmem + PIN_BYTES);         // 2048 halves
    __half* vB  = vA + HID;                               // 4096 halves
    __shared__ float gates[64];
    __shared__ float c1s[UNITS], c2s[UNITS];

    const int tid  = threadIdx.x;
    const int warp = tid >> 5, lane = tid & 31;
    const int k0   = warp * 4;
    const int base = blockIdx.x * UNITS;
    const uint4* vsA = (const uint4*)vA;
    const uint4* vsB = (const uint4*)vB;

    // loop-invariant offsets
    size_t roffA[4], roffB[4];
    int    jrow[4];
#pragma unroll
    for (int r = 0; r < 4; ++r) {
        jrow[r]  = row_j(k0 + r, base);
        roffA[r] = (size_t)jrow[r] * HID + lane * 8;
        roffB[r] = (size_t)jrow[r] * KB  + lane * 8;
    }
    const __half* spin = sW2 + (size_t)k0 * PK + lane * 8;
    float b2v[4];
#pragma unroll
    for (int r = 0; r < 4; ++r) b2v[r] = g_b2[jrow[r]];

    if (tid < UNITS) { c1s[tid] = 0.f; c2s[tid] = 0.f; }

    // ---- one-time: pin first PK columns of this block's 64 W2 rows into SMEM ----
    {
        const int PK8 = PK / 8;
        for (int idx = tid; idx < 64 * PK8; idx += NTHR) {
            int k = idx / PK8, c8 = idx % PK8;
            ((uint4*)(sW2 + (size_t)k * PK))[c8] =
                *(const uint4*)(g_W2 + (size_t)row_j(k, base) * KB + c8 * 8);
        }
    }
    unsigned bar_target = 0;
    __syncthreads();

    for (int t = 0; t < T_STEPS; ++t) {
        const int par = t & 1, prev = par ^ 1;

        // ---- layer 1: vA = h1(t-1) ----
        ((uint2*)vA)[tid] = __ldcg(((const uint2*)g_h1h[prev]) + tid);
        __syncthreads();

        // gx base for this step (lane0 only)
        float gxv[4];
        if (lane == 0) {
            const float* gx = &g_gx[((size_t)t * NBLK + blockIdx.x) * 64];
#pragma unroll
            for (int r = 0; r < 4; ++r) gxv[r] = __ldcs(gx + k0 + r);
        }

        {   // matvecA over K=2048 (streamed W1)
            float s0 = 0.f, s1 = 0.f, s2 = 0.f, s3 = 0.f;
#pragma unroll
            for (int it = 0; it < NIT_A; ++it) {
                LOADV(vsA, it * 32 + lane)
                ROWSTEP_G(g_W1 + roffA[0] + it * 256, s0)
                ROWSTEP_G(g_W1 + roffA[1] + it * 256, s1)
                ROWSTEP_G(g_W1 + roffA[2] + it * 256, s2)
                ROWSTEP_G(g_W1 + roffA[3] + it * 256, s3)
            }
            reduce_store(s0, gxv[0], gates, k0 + 0);
            reduce_store(s1, gxv[1], gates, k0 + 1);
            reduce_store(s2, gxv[2], gates, k0 + 2);
            reduce_store(s3, gxv[3], gates, k0 + 3);
        }

        // prefetch h2(t-1) half of vB (slack = matvecA duration; proven schedule)
        ((uint2*)vB)[512 + tid] = __ldcg(((const uint2*)g_h2h[prev]) + tid);
        __syncthreads();   // gates + vB-upper visible

        // ---- pre-barrier part of layer 2: W_hh2 * h2(t-1), its 8..15 ----
        float sB0 = 0.f, sB1 = 0.f, sB2 = 0.f, sB3 = 0.f;
#pragma unroll
        for (int it = 8; it < 16; ++it) {
            LOADV(vsB, it * 32 + lane)
            ROWSTEP_G(g_W2 + roffB[0] + it * 256, sB0)
            ROWSTEP_G(g_W2 + roffB[1] + it * 256, sB1)
            ROWSTEP_G(g_W2 + roffB[2] + it * 256, sB2)
            ROWSTEP_G(g_W2 + roffB[3] + it * 256, sB3)
        }

        // ---- layer-1 gate nonlinearity ----
        if (tid < UNITS) {
            float gi = sigmoidf_(gates[tid]);
            float gf = sigmoidf_(gates[16 + tid]);
            float gg = tanhf_(gates[32 + tid]);
            float go = sigmoidf_(gates[48 + tid]);
            float c  = gf * c1s[tid] + gi * gg;
            c1s[tid] = c;
            float h  = go * tanhf_(c);
            __stcg(&g_h1h[par][base + tid], __float2half(h));
        }

        // ---- single grid barrier per step ----
        __syncthreads();
        bar_target += NBLK;
        if (tid == 0) {
            __threadfence();
            atomicAdd(&g_cnt, 1u);
            while (*(volatile unsigned*)&g_cnt < bar_target) { }
            __threadfence();
        }
        __syncthreads();

        // ---- post-barrier part of layer 2: vB lower = h1(t) ----
        ((uint2*)vB)[tid] = __ldcg(((const uint2*)g_h1h[par]) + tid);
        __syncthreads();

        {   // pinned its 0..5 (SMEM) + streamed its 6..7
#pragma unroll
            for (int it = 0; it < PIN_IT; ++it) {
                LOADV(vsB, it * 32 + lane)
                ROWSTEP_S(spin + 0 * PK + it * 256, sB0)
                ROWSTEP_S(spin + 1 * PK + it * 256, sB1)
                ROWSTEP_S(spin + 2 * PK + it * 256, sB2)
                ROWSTEP_S(spin + 3 * PK + it * 256, sB3)
            }
#pragma unroll
            for (int it = PIN_IT; it < 8; ++it) {
                LOADV(vsB, it * 32 + lane)
                ROWSTEP_G(g_W2 + roffB[0] + it * 256, sB0)
                ROWSTEP_G(g_W2 + roffB[1] + it * 256, sB1)
                ROWSTEP_G(g_W2 + roffB[2] + it * 256, sB2)
                ROWSTEP_G(g_W2 + roffB[3] + it * 256, sB3)
            }
            reduce_store(sB0, b2v[0], gates, k0 + 0);
            reduce_store(sB1, b2v[1], gates, k0 + 1);
            reduce_store(sB2, b2v[2], gates, k0 + 2);
            reduce_store(sB3, b2v[3], gates, k0 + 3);
        }
        __syncthreads();

        if (tid < UNITS) {
            float gi = sigmoidf_(gates[tid]);
            float gf = sigmoidf_(gates[16 + tid]);
            float gg = tanhf_(gates[32 + tid]);
            float go = sigmoidf_(gates[48 + tid]);
            float c  = gf * c2s[tid] + gi * gg;
            c2s[tid] = c;
            float h  = go * tanhf_(c);
            __stcg(&g_h2h[par][base + tid], __float2half(h));
            __stcs(&g_hist[(size_t)t * HID + base + tid], h);
        }
        // h2(t) publication is ordered by barrier(t+1).
    }
}

// ---------------- deferred output projection ----------------
__global__ void out_kernel(const float* __restrict__ Wlin,
                           const float* __restrict__ blin,
                           float* __restrict__ out) {
    __shared__ float h2s[OB_ROWS][HID];
    const int tid = threadIdx.x, warp = tid >> 5, lane = tid & 31;
    const int t0  = PRE + blockIdx.x * OB_ROWS;

    const float4* src = (const float4*)&g_hist[(size_t)t0 * HID];
    float4*       dst = (float4*)&h2s[0][0];
    for (int i = tid; i < OB_ROWS * HID / 4; i += 256) dst[i] = src[i];
    __syncthreads();

    for (int rr = 0; rr < OB_ROWS; ++rr) {
        for (int j = warp; j < DIN; j += 8) {
            const float* wr = Wlin + (size_t)j * HID;
            float s = 0.f;
#pragma unroll 8
            for (int c = lane; c < HID; c += 32) s += wr[c] * h2s[rr][c];
#pragma unroll
            for (int o = 16; o > 0; o >>= 1) s += __shfl_xor_sync(0xffffffffu, s, o);
            if (lane == 0)
                out[(size_t)(blockIdx.x * OB_ROWS + rr) * DIN + j] = s + blin[j];
        }
    }
}

// ---------------- launch ----------------
extern "C" void kernel_launch(void* const* d_in, const int* in_sizes, int n_in,
                              void* d_out, int out_size) {
    const float* y    = (const float*)d_in[0];
    const float* Wih1 = (const float*)d_in[1];
    const float* Whh1 = (const float*)d_in[2];
    const float* bih1 = (const float*)d_in[3];
    const float* bhh1 = (const float*)d_in[4];
    const float* Wih2 = (const float*)d_in[5];
    const float* Whh2 = (const float*)d_in[6];
    const float* bih2 = (const float*)d_in[7];
    const float* bhh2 = (const float*)d_in[8];
    const float* Wlin = (const float*)d_in[9];
    const float* blin = (const float*)d_in[10];
    float* out = (float*)d_out;

    static int smem_set = 0;
    if (!smem_set) {
        cudaFuncSetAttribute(lstm_main, cudaFuncAttributeMaxDynamicSharedMemorySize, DYN_BYTES);
        smem_set = 1;
    }

    prep_misc<<<32, 256>>>(bih2, bhh2);
    prep_w1<<<(unsigned)(((size_t)G4 * HID + 255) / 256), 256>>>(Whh1);
    prep_w2<<<(unsigned)(((size_t)G4 * KB + 255) / 256), 256>>>(Wih2, Whh2);
    prep_gx<<<dim3(NBLK, 4), NTHR>>>(y, Wih1, bih1, bhh1);
    lstm_main<<<NBLK, NTHR, DYN_BYTES>>>();
    out_kernel<<<OUT_T / OB_ROWS, 256>>>(Wlin, blin, out);
}

// round 6
// speedup vs baseline: 1.1244x; 1.1244x over previous
#include <cuda_runtime.h>
#include <cuda_fp16.h>

#define T_STEPS 4096
#define HID     2048
#define DIN     66
#define PRE     64
#define OUT_T   (T_STEPS - PRE)   // 4032
#define G4      8192              // 4*HID gate rows
#define NBLK    128
#define NTHR    512
#define UNITS   16                // hidden units per block per layer
#define KB      4096              // layer2 K: [h1 ; h2]
#define NIT_A   8                 // 2048 / 256
#define PK      1536              // pinned columns of W2 per row (in SMEM)
#define PIN_IT  6                 // PK / 256
#define OB_ROWS 4
#define GX_TS   256               // timesteps per prep_gx block

#define PIN_BYTES  (64 * PK * 2)                    // 196608
#define DYN_BYTES  (PIN_BYTES + HID * 2 + KB * 2)   // + vA(4KB) + vB(8KB) = 208896
#define GX_SMEM    (GX_TS * 67 * 4)                 // 68608

// ---------------- static device scratch (no allocations allowed) ----------------
__device__ __half g_W1[(size_t)G4 * HID];       // 33.5 MB  W_hh1 fp16
__device__ __half g_W2[(size_t)G4 * KB];        // 67.1 MB  [W_ih2 | W_hh2] fp16
__device__ float  g_b2[G4];
__device__ float  g_gx[(size_t)T_STEPS * G4];   // 134 MB: x@W_ih1^T + b1, block-permuted
__device__ __half g_h1h[2][HID];                // parity double-buffered h1 (half)
__device__ __half g_h2h[2][HID];                // parity double-buffered h2 (half)
__device__ float  g_hist[(size_t)T_STEPS * HID];// h2 history (fp32) for output GEMM
__device__ unsigned g_cnt;                      // grid barrier counter (monotonic)

// row index within block (k=0..63) -> global gate row j
__device__ __forceinline__ int row_j(int k, int base) {
    return ((k >> 4) * HID) + base + (k & 15);
}

// ---------------- prep kernels ----------------
__global__ void prep_w1(const float* __restrict__ Whh1) {
    size_t i = (size_t)blockIdx.x * blockDim.x + threadIdx.x;
    if (i < (size_t)G4 * HID) g_W1[i] = __float2half(Whh1[i]);
}

__global__ void prep_w2(const float* __restrict__ Wih2, const float* __restrict__ Whh2) {
    size_t i = (size_t)blockIdx.x * blockDim.x + threadIdx.x;
    if (i >= (size_t)G4 * KB) return;
    int j = (int)(i / KB);
    int c = (int)(i % KB);
    float v = (c < HID) ? Wih2[(size_t)j * HID + c]
                        : Whh2[(size_t)j * HID + (c - HID)];
    g_W2[i] = __float2half(v);
}

__global__ void prep_misc(const float* __restrict__ bi2, const float* __restrict__ bh2) {
    int i = blockIdx.x * blockDim.x + threadIdx.x;
    if (i < G4) g_b2[i] = bi2[i] + bh2[i];
    if (i < HID) {
        __half z = __float2half(0.f);
        g_h1h[0][i] = z; g_h1h[1][i] = z;
        g_h2h[0][i] = z; g_h2h[1][i] = z;
    }
    if (i == 0) g_cnt = 0u;
}

// gates_x[t, blk, k] = b1[j] + sum_c y[t,c] * W_ih1[j,c]   (block-local row order k)
// grid: (NBLK, 16); block handles 64 rows x GX_TS timesteps; y tile staged in SMEM.
__global__ void prep_gx(const float* __restrict__ y, const float* __restrict__ Wih1,
                        const float* __restrict__ bi1, const float* __restrict__ bh1) {
    __shared__ float sW[64][68];   // padded to 17 float4 per row
    __shared__ float sb[64];
    extern __shared__ float ys[];  // [GX_TS][67] padded stride (67 % 32 = 3: conflict-free)
    const int b = blockIdx.x, base = b * UNITS;
    const int t0 = blockIdx.y * GX_TS;
    const int tid = threadIdx.x;

    for (int idx = tid; idx < 64 * 68; idx += blockDim.x) {
        int k = idx / 68, c = idx % 68;
        sW[k][c] = (c < DIN) ? Wih1[(size_t)row_j(k, base) * DIN + c] : 0.f;
    }
    if (tid < 64) {
        int j = row_j(tid, base);
        sb[tid] = bi1[j] + bh1[j];
    }
    // coalesced stage of y[t0 .. t0+GX_TS) into padded SMEM
    for (int i = tid; i < GX_TS * DIN; i += blockDim.x)
        ys[(i / DIN) * 67 + (i % DIN)] = y[(size_t)t0 * DIN + i];
    __syncthreads();

    const int t = t0 + tid;        // one timestep per thread (blockDim.x == GX_TS)
    float xv[68];
#pragma unroll
    for (int c = 0; c < DIN; ++c) xv[c] = ys[tid * 67 + c];
    xv[66] = 0.f; xv[67] = 0.f;
    float* outp = &g_gx[((size_t)t * NBLK + b) * 64];
    for (int k = 0; k < 64; ++k) {
        float s = sb[k];
#pragma unroll
        for (int c4 = 0; c4 < 17; ++c4) {
            float4 w = *(const float4*)&sW[k][c4 * 4];
            s += w.x * xv[c4*4] + w.y * xv[c4*4+1] + w.z * xv[c4*4+2] + w.w * xv[c4*4+3];
        }
        outp[k] = s;
    }
}

// ---------------- math helpers ----------------
__device__ __forceinline__ float sigmoidf_(float x) { return 1.f / (1.f + __expf(-x)); }
__device__ __forceinline__ float tanhf_(float x) {
    float e = __expf(-2.f * fabsf(x));
    float r = (1.f - e) / (1.f + e);
    return (x < 0.f) ? -r : r;
}

#define ROWSTEP(P, ACC)                                                     \
    {                                                                       \
        uint4 wv = *(const uint4*)(P);                                      \
        __half2 a = __hmul2(*(__half2*)&wv.x, h0);                          \
        a = __hfma2(*(__half2*)&wv.y, h1, a);                               \
        a = __hfma2(*(__half2*)&wv.z, h2, a);                               \
        a = __hfma2(*(__half2*)&wv.w, h3, a);                               \
        float2 f = __half22float2(a);                                       \
        ACC += f.x; ACC += f.y;                                             \
    }
#define LOADV(vs, idx)                                                      \
    uint4 hv = (vs)[idx];                                                   \
    __half2 h0 = *(__half2*)&hv.x, h1 = *(__half2*)&hv.y,                   \
            h2 = *(__half2*)&hv.z, h3 = *(__half2*)&hv.w;

__device__ __forceinline__ void reduce_store(float v, float add, float* gates, int k) {
#pragma unroll
    for (int o = 16; o > 0; o >>= 1) v += __shfl_xor_sync(0xffffffffu, v, o);
    if ((threadIdx.x & 31) == 0) gates[k] = v + add;
}

// ---------------- main persistent recurrent kernel ----------------
__global__ void __launch_bounds__(NTHR, 1) lstm_main() {
    extern __shared__ __align__(16) unsigned char dynsmem[];
    __half* sW2 = (__half*)dynsmem;                       // 64 x PK pinned W2 slice
    __half* vA  = (__half*)(dynsmem + PIN_BYTES);         // 2048 halves
    __half* vB  = vA + HID;                               // 4096 halves
    __shared__ float gates[64];
    __shared__ float c1s[UNITS], c2s[UNITS];

    const int tid  = threadIdx.x;
    const int warp = tid >> 5, lane = tid & 31;
    const int k0   = warp * 4;
    const int base = blockIdx.x * UNITS;
    const uint4* vsA = (const uint4*)vA;
    const uint4* vsB = (const uint4*)vB;

    size_t roffA[4], roffB[4];
    int    jrow[4];
#pragma unroll
    for (int r = 0; r < 4; ++r) {
        jrow[r]  = row_j(k0 + r, base);
        roffA[r] = (size_t)jrow[r] * HID + lane * 8;
        roffB[r] = (size_t)jrow[r] * KB  + lane * 8;
    }
    const __half* spin = sW2 + (size_t)k0 * PK + lane * 8;
    float b2v[4];
#pragma unroll
    for (int r = 0; r < 4; ++r) b2v[r] = g_b2[jrow[r]];

    if (tid < UNITS) { c1s[tid] = 0.f; c2s[tid] = 0.f; }

    // ---- one-time: pin first PK columns of this block's 64 W2 rows into SMEM ----
    {
        const int PK8 = PK / 8;
        for (int idx = tid; idx < 64 * PK8; idx += NTHR) {
            int k = idx / PK8, c8 = idx % PK8;
            ((uint4*)(sW2 + (size_t)k * PK))[c8] =
                *(const uint4*)(g_W2 + (size_t)row_j(k, base) * KB + c8 * 8);
        }
    }
    unsigned bar_target = 0;
    __syncthreads();

    for (int t = 0; t < T_STEPS; ++t) {
        const int par = t & 1, prev = par ^ 1;

        // ---- layer 1: vA = h1(t-1) ----
        ((uint2*)vA)[tid] = __ldcg(((const uint2*)g_h1h[prev]) + tid);
        __syncthreads();

        float gxv[4];
        if (lane == 0) {
            const float* gx = &g_gx[((size_t)t * NBLK + blockIdx.x) * 64];
#pragma unroll
            for (int r = 0; r < 4; ++r) gxv[r] = __ldcs(gx + k0 + r);
        }

        {   // matvecA over K=2048 (streamed W1)
            float s0 = 0.f, s1 = 0.f, s2 = 0.f, s3 = 0.f;
#pragma unroll
            for (int it = 0; it < NIT_A; ++it) {
                LOADV(vsA, it * 32 + lane)
                ROWSTEP(g_W1 + roffA[0] + it * 256, s0)
                ROWSTEP(g_W1 + roffA[1] + it * 256, s1)
                ROWSTEP(g_W1 + roffA[2] + it * 256, s2)
                ROWSTEP(g_W1 + roffA[3] + it * 256, s3)
            }
            reduce_store(s0, gxv[0], gates, k0 + 0);
            reduce_store(s1, gxv[1], gates, k0 + 1);
            reduce_store(s2, gxv[2], gates, k0 + 2);
            reduce_store(s3, gxv[3], gates, k0 + 3);
        }

        // prefetch h2(t-1) half of vB (slack = matvecA duration; proven window)
        ((uint2*)vB)[512 + tid] = __ldcg(((const uint2*)g_h2h[prev]) + tid);
        __syncthreads();   // gates + vB-upper visible

        // ---- layer-1 gate nonlinearity + h1 publish ----
        if (tid < UNITS) {
            float gi = sigmoidf_(gates[tid]);
            float gf = sigmoidf_(gates[16 + tid]);
            float gg = tanhf_(gates[32 + tid]);
            float go = sigmoidf_(gates[48 + tid]);
            float c  = gf * c1s[tid] + gi * gg;
            c1s[tid] = c;
            float h  = go * tanhf_(c);
            __stcg(&g_h1h[par][base + tid], __float2half(h));
        }
        __syncthreads();   // h1 stores issued block-wide

        // ---- barrier ARRIVE (immediately: no streaming delays arrival) ----
        bar_target += NBLK;
        if (tid == 0) {
            __threadfence();
            atomicAdd(&g_cnt, 1u);
        }

        // ---- overlap: W_hh2 * h2(t-1) (its 8..15, 32 MB stream) hides the wait ----
        float sB0 = 0.f, sB1 = 0.f, sB2 = 0.f, sB3 = 0.f;
#pragma unroll
        for (int it = 8; it < 16; ++it) {
            LOADV(vsB, it * 32 + lane)
            ROWSTEP(g_W2 + roffB[0] + it * 256, sB0)
            ROWSTEP(g_W2 + roffB[1] + it * 256, sB1)
            ROWSTEP(g_W2 + roffB[2] + it * 256, sB2)
            ROWSTEP(g_W2 + roffB[3] + it * 256, sB3)
        }

        // ---- barrier WAIT ----
        if (tid == 0) {
            while (*(volatile unsigned*)&g_cnt < bar_target) { }
            __threadfence();
        }
        __syncthreads();

        // ---- post-wait: vB lower = h1(t); pinned + short streamed tail ----
        ((uint2*)vB)[tid] = __ldcg(((const uint2*)g_h1h[par]) + tid);
        __syncthreads();

        {
#pragma unroll
            for (int it = 0; it < PIN_IT; ++it) {
                LOADV(vsB, it * 32 + lane)
                ROWSTEP(spin + 0 * PK + it * 256, sB0)
                ROWSTEP(spin + 1 * PK + it * 256, sB1)
                ROWSTEP(spin + 2 * PK + it * 256, sB2)
                ROWSTEP(spin + 3 * PK + it * 256, sB3)
            }
#pragma unroll
            for (int it = PIN_IT; it < 8; ++it) {
                LOADV(vsB, it * 32 + lane)
                ROWSTEP(g_W2 + roffB[0] + it * 256, sB0)
                ROWSTEP(g_W2 + roffB[1] + it * 256, sB1)
                ROWSTEP(g_W2 + roffB[2] + it * 256, sB2)
                ROWSTEP(g_W2 + roffB[3] + it * 256, sB3)
            }
            reduce_store(sB0, b2v[0], gates, k0 + 0);
            reduce_store(sB1, b2v[1], gates, k0 + 1);
            reduce_store(sB2, b2v[2], gates, k0 + 2);
            reduce_store(sB3, b2v[3], gates, k0 + 3);
        }
        __syncthreads();

        if (tid < UNITS) {
            float gi = sigmoidf_(gates[tid]);
            float gf = sigmoidf_(gates[16 + tid]);
            float gg = tanhf_(gates[32 + tid]);
            float go = sigmoidf_(gates[48 + tid]);
            float c  = gf * c2s[tid] + gi * gg;
            c2s[tid] = c;
            float h  = go * tanhf_(c);
            __stcg(&g_h2h[par][base + tid], __float2half(h));
            __stcs(&g_hist[(size_t)t * HID + base + tid], h);
        }
        // h2(t) publication consumed at t+1 in the proven prefetch window.
    }
}

// ---------------- deferred output projection ----------------
__global__ void out_kernel(const float* __restrict__ Wlin,
                           const float* __restrict__ blin,
                           float* __restrict__ out) {
    __shared__ float h2s[OB_ROWS][HID];
    const int tid = threadIdx.x, warp = tid >> 5, lane = tid & 31;
    const int t0  = PRE + blockIdx.x * OB_ROWS;

    const float4* src = (const float4*)&g_hist[(size_t)t0 * HID];
    float4*       dst = (float4*)&h2s[0][0];
    for (int i = tid; i < OB_ROWS * HID / 4; i += 256) dst[i] = src[i];
    __syncthreads();

    for (int rr = 0; rr < OB_ROWS; ++rr) {
        for (int j = warp; j < DIN; j += 8) {
            const float* wr = Wlin + (size_t)j * HID;
            float s = 0.f;
#pragma unroll 8
            for (int c = lane; c < HID; c += 32) s += wr[c] * h2s[rr][c];
#pragma unroll
            for (int o = 16; o > 0; o >>= 1) s += __shfl_xor_sync(0xffffffffu, s, o);
            if (lane == 0)
                out[(size_t)(blockIdx.x * OB_ROWS + rr) * DIN + j] = s + blin[j];
        }
    }
}

// ---------------- launch ----------------
extern "C" void kernel_launch(void* const* d_in, const int* in_sizes, int n_in,
                              void* d_out, int out_size) {
    const float* y    = (const float*)d_in[0];
    const float* Wih1 = (const float*)d_in[1];
    const float* Whh1 = (const float*)d_in[2];
    const float* bih1 = (const float*)d_in[3];
    const float* bhh1 = (const float*)d_in[4];
    const float* Wih2 = (const float*)d_in[5];
    const float* Whh2 = (const float*)d_in[6];
    const float* bih2 = (const float*)d_in[7];
    const float* bhh2 = (const float*)d_in[8];
    const float* Wlin = (const float*)d_in[9];
    const float* blin = (const float*)d_in[10];
    float* out = (float*)d_out;

    static int smem_set = 0;
    if (!smem_set) {
        cudaFuncSetAttribute(lstm_main, cudaFuncAttributeMaxDynamicSharedMemorySize, DYN_BYTES);
        cudaFuncSetAttribute(prep_gx,   cudaFuncAttributeMaxDynamicSharedMemorySize, GX_SMEM);
        smem_set = 1;
    }

    prep_misc<<<32, 256>>>(bih2, bhh2);
    prep_w1<<<(unsigned)(((size_t)G4 * HID + 255) / 256), 256>>>(Whh1);
    prep_w2<<<(unsigned)(((size_t)G4 * KB + 255) / 256), 256>>>(Wih2, Whh2);
    prep_gx<<<dim3(NBLK, T_STEPS / GX_TS), GX_TS, GX_SMEM>>>(y, Wih1, bih1, bhh1);
    lstm_main<<<NBLK, NTHR, DYN_BYTES>>>();
    out_kernel<<<OUT_T / OB_ROWS, 256>>>(Wlin, blin, out);
}